// round 1
// baseline (speedup 1.0000x reference)
#include <cuda_runtime.h>
#include <math.h>

#define DD 8
#define BB 4096
#define VV 1024
#define KSEL 102
#define TPB 256

// samples[d*BB + b]
__device__ int g_samples[DD * BB];

__device__ __forceinline__ unsigned key_of(float x) {
    unsigned u = __float_as_uint(x);
    // order-preserving transform: monotone unsigned key
    return (u & 0x80000000u) ? ~u : (u | 0x80000000u);
}

__global__ void __launch_bounds__(TPB)
decode_row_kernel(const float* __restrict__ logits,
                  const float* __restrict__ uni,
                  const int*   __restrict__ curv,
                  float*       __restrict__ probs_out,   // may be null
                  int write_probs)
{
    const int row = blockIdx.x;            // row = d*BB + b
    const int tid = threadIdx.x;
    const float* lrow = logits + (size_t)row * VV;
    const float* urow = uni    + (size_t)row * VV;
    const int cv = curv[row];

    // ---- load 4 logits + 4 uniforms per thread (coalesced float4) ----
    float4 l4 = ((const float4*)lrow)[tid];
    float4 u4 = ((const float4*)urow)[tid];
    float vals[4] = {l4.x, l4.y, l4.z, l4.w};
    float us[4]   = {u4.x, u4.y, u4.z, u4.w};
    const int base = tid * 4;
    const float NEG = -INFINITY;
    #pragma unroll
    for (int j = 0; j < 4; j++) {
        int g = base + j;
        if (g < cv || g == 0) vals[j] = NEG;
    }
    unsigned keys[4];
    #pragma unroll
    for (int j = 0; j < 4; j++) keys[j] = key_of(vals[j]);

    __shared__ unsigned hist[256];
    __shared__ unsigned cum[256];
    __shared__ unsigned sPrefix;
    __shared__ int      sKK;
    __shared__ float    sRv[256];
    __shared__ int      sRi[256];

    // ---- radix select: find key of the KSEL-th largest value ----
    unsigned prefix = 0;
    int kk = KSEL;
    #pragma unroll
    for (int pass = 0; pass < 4; pass++) {
        const int shift = 24 - 8 * pass;
        const unsigned pmask = (pass == 0) ? 0u : (0xFFFFFFFFu << (shift + 8));

        hist[tid] = 0;
        __syncthreads();
        #pragma unroll
        for (int j = 0; j < 4; j++) {
            if ((keys[j] & pmask) == (prefix & pmask))
                atomicAdd(&hist[(keys[j] >> shift) & 0xFFu], 1u);
        }
        __syncthreads();

        // suffix sums: cum[b] = sum_{j >= b} hist[j]  (Hillis-Steele, 8 steps)
        cum[tid] = hist[tid];
        __syncthreads();
        #pragma unroll
        for (int off = 1; off < 256; off <<= 1) {
            unsigned add = (tid + off < 256) ? cum[tid + off] : 0u;
            __syncthreads();
            cum[tid] += add;
            __syncthreads();
        }

        // locate the bin containing the kk-th (from top) element
        {
            unsigned c       = cum[tid];
            unsigned chigher = (tid < 255) ? cum[tid + 1] : 0u;
            if ((int)c >= kk && (int)chigher < kk) {
                sPrefix = prefix | ((unsigned)tid << shift);
                sKK     = kk - (int)chigher;
            }
        }
        __syncthreads();
        prefix = sPrefix;
        kk     = sKK;
        __syncthreads();
    }
    const unsigned kthkey = prefix;   // exact key of kth-largest value

    // ---- row max (block reduce) ----
    float lm = fmaxf(fmaxf(vals[0], vals[1]), fmaxf(vals[2], vals[3]));
    sRv[tid] = lm;
    __syncthreads();
    #pragma unroll
    for (int off = 128; off > 0; off >>= 1) {
        if (tid < off) sRv[tid] = fmaxf(sRv[tid], sRv[tid + off]);
        __syncthreads();
    }
    const float rowmax = sRv[0];
    __syncthreads();

    // ---- sum of exp over kept (vals >= kth) ----
    float ls = 0.0f;
    float sh[4];
    #pragma unroll
    for (int j = 0; j < 4; j++) {
        sh[j] = vals[j] - rowmax;
        if (keys[j] >= kthkey) ls += expf(sh[j]);
    }
    sRv[tid] = ls;
    __syncthreads();
    #pragma unroll
    for (int off = 128; off > 0; off >>= 1) {
        if (tid < off) sRv[tid] += sRv[tid + off];
        __syncthreads();
    }
    const float logZ = logf(sRv[0]);
    __syncthreads();

    // ---- probs + gumbel-max (gumbel only for kept elements) ----
    float bestv = -INFINITY;
    int   besti = VV;
    float outp[4];
    #pragma unroll
    for (int j = 0; j < 4; j++) {
        if (keys[j] >= kthkey) {
            float lp = sh[j] - logZ;
            outp[j] = expf(lp);
            float gum = -logf(-logf(us[j] + 1e-20f) + 1e-20f);
            float sc  = lp + gum;
            int g = base + j;
            if (sc > bestv || (sc == bestv && g < besti)) { bestv = sc; besti = g; }
        } else {
            outp[j] = 0.0f;
        }
    }
    if (write_probs) {
        float* prow = probs_out + (size_t)row * VV;
        ((float4*)prow)[tid] = make_float4(outp[0], outp[1], outp[2], outp[3]);
    }

    // ---- block argmax (first-index tie break) ----
    sRv[tid] = bestv;
    sRi[tid] = besti;
    __syncthreads();
    #pragma unroll
    for (int off = 128; off > 0; off >>= 1) {
        if (tid < off) {
            float ov = sRv[tid + off]; int oi = sRi[tid + off];
            if (ov > sRv[tid] || (ov == sRv[tid] && oi < sRi[tid])) {
                sRv[tid] = ov; sRi[tid] = oi;
            }
        }
        __syncthreads();
    }
    if (tid == 0) g_samples[row] = sRi[0];
}

// tokens[b*DD + d] = (d==0 || samples[0][b]==NOTE_TYPE) ? samples[d][b] : 0
__global__ void tokens_kernel(float* __restrict__ out)
{
    int i = blockIdx.x * blockDim.x + threadIdx.x;
    if (i >= BB * DD) return;
    int b = i / DD;
    int d = i % DD;
    int s0 = g_samples[b];                 // d = 0
    int sd = g_samples[d * BB + b];
    int tok = (d == 0 || s0 == 1) ? sd : 0;
    out[i] = (float)tok;
}

extern "C" void kernel_launch(void* const* d_in, const int* in_sizes, int n_in,
                              void* d_out, int out_size)
{
    const float* logits = (const float*)d_in[0];
    const float* u      = (const float*)d_in[1];
    const int*   cv     = (const int*)d_in[2];
    float* out = (float*)d_out;

    const long long n_probs  = (long long)DD * BB * VV;   // 33554432
    const long long n_tokens = (long long)BB * DD;        // 32768

    float* tok_ptr   = nullptr;
    float* probs_ptr = nullptr;
    if ((long long)out_size == n_probs + n_tokens) {
        tok_ptr   = out;                 // tokens.T first (reference return order)
        probs_ptr = out + n_tokens;
    } else if ((long long)out_size == n_probs) {
        probs_ptr = out;
    } else {
        tok_ptr = out;                   // tokens only
    }

    decode_row_kernel<<<DD * BB, TPB>>>(logits, u, cv,
                                        probs_ptr, probs_ptr != nullptr ? 1 : 0);
    if (tok_ptr != nullptr) {
        tokens_kernel<<<(BB * DD + 255) / 256, 256>>>(tok_ptr);
    }
}

// round 2
// speedup vs baseline: 1.1957x; 1.1957x over previous
#include <cuda_runtime.h>
#include <math.h>

#define DD 8
#define BB 4096
#define VV 1024
#define KSEL 102
#define ROWS (DD * BB)

__device__ int g_samples[ROWS];

__device__ __forceinline__ unsigned key_of(float x) {
    unsigned u = __float_as_uint(x);
    return (u & 0x80000000u) ? ~u : (u | 0x80000000u);
}
__device__ __forceinline__ float inv_key(unsigned k) {
    unsigned b = (k & 0x80000000u) ? (k & 0x7FFFFFFFu) : ~k;
    return __uint_as_float(b);
}

__global__ void __launch_bounds__(256, 2)
decode_warp_kernel(const float* __restrict__ logits,
                   const float* __restrict__ uni,
                   const int*   __restrict__ curv,
                   float*       __restrict__ probs_out,
                   int write_probs)
{
    const int warp = threadIdx.x >> 5;
    const int lane = threadIdx.x & 31;
    const int row  = blockIdx.x * 8 + warp;

    const float* lrow = logits + (size_t)row * VV;
    const float* urow = uni    + (size_t)row * VV;
    const int cv = curv[row];
    const unsigned FULL = 0xFFFFFFFFu;

    // ---- load 32 logits + 32 uniforms per lane (coalesced float4) ----
    // lane owns elements g = (i*32+lane)*4 + j, i in [0,8), j in [0,4)
    unsigned keys[32];
    float4 u4[8];
    #pragma unroll
    for (int i = 0; i < 8; i++) {
        float4 l4 = ((const float4*)lrow)[i * 32 + lane];
        u4[i]     = ((const float4*)urow)[i * 32 + lane];
        int g = (i * 32 + lane) * 4;
        float v0 = (g + 0 < cv || g + 0 == 0) ? -INFINITY : l4.x;
        float v1 = (g + 1 < cv)               ? -INFINITY : l4.y;
        float v2 = (g + 2 < cv)               ? -INFINITY : l4.z;
        float v3 = (g + 3 < cv)               ? -INFINITY : l4.w;
        keys[i * 4 + 0] = key_of(v0);
        keys[i * 4 + 1] = key_of(v1);
        keys[i * 4 + 2] = key_of(v2);
        keys[i * 4 + 3] = key_of(v3);
    }

    // ---- exact kth-largest key via bitwise binary search ----
    // T ends as the largest threshold with count(keys >= T) >= KSEL;
    // early exit when count == KSEL (kept set already equals {key >= kth}).
    unsigned T = 0;
    for (int bit = 31; bit >= 0; --bit) {
        unsigned T2 = T | (1u << bit);
        int c = 0;
        #pragma unroll
        for (int e = 0; e < 32; e++) c += (keys[e] >= T2) ? 1 : 0;
        c = __reduce_add_sync(FULL, c);
        if (c >= KSEL) {
            T = T2;
            if (c == KSEL) break;
        }
    }

    // ---- row max (via max key, order-preserving) ----
    unsigned mk = 0;
    #pragma unroll
    for (int e = 0; e < 32; e++) mk = max(mk, keys[e]);
    #pragma unroll
    for (int off = 16; off > 0; off >>= 1)
        mk = max(mk, __shfl_xor_sync(FULL, mk, off));
    const float rowmax = inv_key(mk);

    // ---- sum of exp over kept ----
    float s = 0.0f;
    #pragma unroll
    for (int e = 0; e < 32; e++) {
        if (keys[e] >= T) s += expf(inv_key(keys[e]) - rowmax);
    }
    #pragma unroll
    for (int off = 16; off > 0; off >>= 1)
        s += __shfl_xor_sync(FULL, s, off);
    const float logZ = logf(s);

    // ---- probs write + gumbel-max (gumbel only for kept) ----
    float bestv = -INFINITY;
    int   besti = VV;
    float* prow = probs_out + (size_t)row * VV;
    #pragma unroll
    for (int i = 0; i < 8; i++) {
        float uu[4] = {u4[i].x, u4[i].y, u4[i].z, u4[i].w};
        float o[4];
        int gbase = (i * 32 + lane) * 4;
        #pragma unroll
        for (int j = 0; j < 4; j++) {
            int e = i * 4 + j;
            if (keys[e] >= T) {
                float lp = inv_key(keys[e]) - rowmax - logZ;
                o[j] = expf(lp);
                float gum = -logf(-logf(uu[j] + 1e-20f) + 1e-20f);
                float sc  = lp + gum;
                int g = gbase + j;
                if (sc > bestv || (sc == bestv && g < besti)) { bestv = sc; besti = g; }
            } else {
                o[j] = 0.0f;
            }
        }
        if (write_probs)
            ((float4*)prow)[i * 32 + lane] = make_float4(o[0], o[1], o[2], o[3]);
    }

    // ---- warp argmax (first-index tie break) ----
    #pragma unroll
    for (int off = 16; off > 0; off >>= 1) {
        float ov = __shfl_xor_sync(FULL, bestv, off);
        int   oi = __shfl_xor_sync(FULL, besti, off);
        if (ov > bestv || (ov == bestv && oi < besti)) { bestv = ov; besti = oi; }
    }
    if (lane == 0) g_samples[row] = besti;
}

// tokens[b*DD + d] = (d==0 || samples[0][b]==NOTE_TYPE) ? samples[d][b] : 0
__global__ void tokens_kernel(float* __restrict__ out)
{
    int i = blockIdx.x * blockDim.x + threadIdx.x;
    if (i >= BB * DD) return;
    int b = i / DD;
    int d = i % DD;
    int s0 = g_samples[b];
    int sd = g_samples[d * BB + b];
    int tok = (d == 0 || s0 == 1) ? sd : 0;
    out[i] = (float)tok;
}

extern "C" void kernel_launch(void* const* d_in, const int* in_sizes, int n_in,
                              void* d_out, int out_size)
{
    const float* logits = (const float*)d_in[0];
    const float* u      = (const float*)d_in[1];
    const int*   cv     = (const int*)d_in[2];
    float* out = (float*)d_out;

    const long long n_probs  = (long long)DD * BB * VV;
    const long long n_tokens = (long long)BB * DD;

    float* tok_ptr   = nullptr;
    float* probs_ptr = nullptr;
    if ((long long)out_size == n_probs + n_tokens) {
        tok_ptr   = out;
        probs_ptr = out + n_tokens;
    } else if ((long long)out_size == n_probs) {
        probs_ptr = out;
    } else {
        tok_ptr = out;
    }

    decode_warp_kernel<<<ROWS / 8, 256>>>(logits, u, cv,
                                          probs_ptr, probs_ptr != nullptr ? 1 : 0);
    if (tok_ptr != nullptr) {
        tokens_kernel<<<(BB * DD + 255) / 256, 256>>>(tok_ptr);
    }
}

// round 3
// speedup vs baseline: 1.7265x; 1.4440x over previous
#include <cuda_runtime.h>
#include <math.h>

#define DD 8
#define BB 4096
#define VV 1024
#define KSEL 102
#define ROWS (DD * BB)
#define FULLM 0xFFFFFFFFu

__device__ int g_samples[ROWS];

static __device__ __forceinline__ unsigned key_of(float x) {
    unsigned u = __float_as_uint(x);
    return (u & 0x80000000u) ? ~u : (u | 0x80000000u);
}
static __device__ __forceinline__ float inv_key(unsigned k) {
    return __uint_as_float((k & 0x80000000u) ? (k & 0x7FFFFFFFu) : ~k);
}

__global__ void __launch_bounds__(256)
decode_kernel(const float* __restrict__ logits,
              const float* __restrict__ uni,
              const int*   __restrict__ curv,
              float*       __restrict__ probs_out,
              int write_probs)
{
    __shared__ unsigned hist[8][256];
    const int warp = threadIdx.x >> 5;
    const int lane = threadIdx.x & 31;
    const int row  = blockIdx.x * 8 + warp;
    const float* lrow = logits + (size_t)row * VV;
    const float* urow = uni    + (size_t)row * VV;
    const int cv = curv[row];
    unsigned* h = hist[warp];

    // ---- load logits, mask, build order-preserving keys (32/lane) ----
    unsigned keys[32];
    #pragma unroll
    for (int i = 0; i < 8; i++) {
        float4 l4 = ((const float4*)lrow)[i * 32 + lane];
        int g = (i * 32 + lane) * 4;
        float v0 = (g + 0 < cv || g == 0) ? -INFINITY : l4.x;
        float v1 = (g + 1 < cv)           ? -INFINITY : l4.y;
        float v2 = (g + 2 < cv)           ? -INFINITY : l4.z;
        float v3 = (g + 3 < cv)           ? -INFINITY : l4.w;
        keys[i * 4 + 0] = key_of(v0);
        keys[i * 4 + 1] = key_of(v1);
        keys[i * 4 + 2] = key_of(v2);
        keys[i * 4 + 3] = key_of(v3);
    }

    // ================= radix select: pass 1 (top 8 bits) =================
    #pragma unroll
    for (int i = 0; i < 8; i++) h[i * 32 + lane] = 0;
    __syncwarp();
    #pragma unroll
    for (int e = 0; e < 32; e++)
        atomicAdd(&h[keys[e] >> 24], 1u);
    __syncwarp();

    int kk = KSEL;
    int b1; int kk2; // bin + remaining rank within bin

    {
        unsigned v[8]; unsigned tot = 0;
        #pragma unroll
        for (int i = 0; i < 8; i++) { v[i] = h[lane * 8 + i]; tot += v[i]; }
        unsigned suf = tot;
        #pragma unroll
        for (int off = 1; off < 32; off <<= 1) {
            unsigned t = __shfl_down_sync(FULLM, suf, off);
            if (lane + off < 32) suf += t;
        }
        unsigned tail = suf - tot;            // sum over lanes > lane
        int fi = -1; unsigned fnext = 0;
        unsigned run = tail;
        #pragma unroll
        for (int i = 7; i >= 0; i--) {
            unsigned Snext = run;
            run += v[i];
            if ((int)run >= kk && (int)Snext < kk) { fi = i; fnext = Snext; }
        }
        unsigned bal = __ballot_sync(FULLM, fi >= 0);
        int src = __ffs(bal) - 1;
        b1  = __shfl_sync(FULLM, fi, src) + src * 8;
        kk2 = kk - (int)__shfl_sync(FULLM, fnext, src);
    }

    // ================= radix select: pass 2 (bits 23:16) =================
    #pragma unroll
    for (int i = 0; i < 8; i++) h[i * 32 + lane] = 0;
    __syncwarp();
    #pragma unroll
    for (int e = 0; e < 32; e++)
        if ((int)(keys[e] >> 24) == b1)
            atomicAdd(&h[(keys[e] >> 16) & 0xFFu], 1u);
    __syncwarp();

    int b2; int kk3; int c2;
    {
        unsigned v[8]; unsigned tot = 0;
        #pragma unroll
        for (int i = 0; i < 8; i++) { v[i] = h[lane * 8 + i]; tot += v[i]; }
        unsigned suf = tot;
        #pragma unroll
        for (int off = 1; off < 32; off <<= 1) {
            unsigned t = __shfl_down_sync(FULLM, suf, off);
            if (lane + off < 32) suf += t;
        }
        unsigned tail = suf - tot;
        int fi = -1; unsigned fnext = 0; unsigned fcnt = 0;
        unsigned run = tail;
        #pragma unroll
        for (int i = 7; i >= 0; i--) {
            unsigned Snext = run;
            run += v[i];
            if ((int)run >= kk2 && (int)Snext < kk2) { fi = i; fnext = Snext; fcnt = v[i]; }
        }
        unsigned bal = __ballot_sync(FULLM, fi >= 0);
        int src = __ffs(bal) - 1;
        b2  = __shfl_sync(FULLM, fi, src) + src * 8;
        kk3 = kk2 - (int)__shfl_sync(FULLM, fnext, src);
        c2  = (int)__shfl_sync(FULLM, fcnt, src);
    }

    const unsigned P16 = ((unsigned)b1 << 8) | (unsigned)b2;
    unsigned T;
    if (c2 == kk3) {
        T = P16 << 16;      // keep the whole 16-bit bin (common fast path)
    } else {
        // rare: resolve exact kth among elements sharing the 16-bit prefix
        unsigned cur = 0xFFFFFFFFu;   // exclusive upper bound (0xFFFFFFFF = NaN key, never occurs)
        int rem = kk3;
        while (rem > 0) {
            unsigned m = 0;
            #pragma unroll
            for (int e = 0; e < 32; e++) {
                unsigned k = keys[e];
                if ((k >> 16) == P16 && k < cur) m = max(m, k);
            }
            #pragma unroll
            for (int off = 16; off > 0; off >>= 1)
                m = max(m, __shfl_xor_sync(FULLM, m, off));
            int c = 0;
            #pragma unroll
            for (int e = 0; e < 32; e++) c += (keys[e] == m) ? 1 : 0;
            #pragma unroll
            for (int off = 16; off > 0; off >>= 1)
                c += __shfl_xor_sync(FULLM, c, off);
            rem -= c;
            cur = m;
        }
        T = cur;
    }

    // ---- row max (order-preserving key max) ----
    unsigned mk = 0;
    #pragma unroll
    for (int e = 0; e < 32; e++) mk = max(mk, keys[e]);
    #pragma unroll
    for (int off = 16; off > 0; off >>= 1)
        mk = max(mk, __shfl_xor_sync(FULLM, mk, off));
    const float rowmax = inv_key(mk);

    // ---- kept mask + sum of exp (cheap __expf; logZ is a common constant) ----
    unsigned km = 0;
    float s = 0.0f;
    #pragma unroll
    for (int e = 0; e < 32; e++) {
        bool kept = keys[e] >= T;
        km |= kept ? (1u << e) : 0u;
        float ex = __expf(inv_key(keys[e]) - rowmax);
        s += kept ? ex : 0.0f;
    }
    #pragma unroll
    for (int off = 16; off > 0; off >>= 1)
        s += __shfl_xor_sync(FULLM, s, off);
    const float logZ = logf(s);

    // ---- probs write: predicated __expf + vector stores ----
    if (write_probs) {
        float* prow = probs_out + (size_t)row * VV;
        #pragma unroll
        for (int i = 0; i < 8; i++) {
            float o[4];
            #pragma unroll
            for (int j = 0; j < 4; j++) {
                int e = i * 4 + j;
                float p = __expf((inv_key(keys[e]) - rowmax) - logZ);
                o[j] = (keys[e] >= T) ? p : 0.0f;
            }
            ((float4*)prow)[i * 32 + lane] = make_float4(o[0], o[1], o[2], o[3]);
        }
    }

    // ---- gumbel-max over kept only (ffs loop, ~3 trips/lane avg) ----
    float bestv = -INFINITY;
    int   besti = VV;
    unsigned m = km;
    while (m) {
        int e = __ffs(m) - 1;
        m &= m - 1;
        int g = ((e >> 2) * 128) + (lane << 2) + (e & 3);
        float val = __ldg(lrow + g);              // L1 hit
        float uu  = __ldg(urow + g);              // only kept u is ever read
        float lp  = (val - rowmax) - logZ;
        float gum = -logf(-logf(uu + 1e-20f) + 1e-20f);
        float sc  = lp + gum;
        if (sc > bestv || (sc == bestv && g < besti)) { bestv = sc; besti = g; }
    }
    #pragma unroll
    for (int off = 16; off > 0; off >>= 1) {
        float ov = __shfl_xor_sync(FULLM, bestv, off);
        int   oi = __shfl_xor_sync(FULLM, besti, off);
        if (ov > bestv || (ov == bestv && oi < besti)) { bestv = ov; besti = oi; }
    }
    if (lane == 0) g_samples[row] = besti;
}

// tokens[b*DD + d] = (d==0 || samples[0][b]==NOTE_TYPE) ? samples[d][b] : 0
__global__ void tokens_kernel(float* __restrict__ out)
{
    int i = blockIdx.x * blockDim.x + threadIdx.x;
    if (i >= BB * DD) return;
    int b = i / DD;
    int d = i % DD;
    int s0 = g_samples[b];
    int sd = g_samples[d * BB + b];
    int tok = (d == 0 || s0 == 1) ? sd : 0;
    out[i] = (float)tok;
}

extern "C" void kernel_launch(void* const* d_in, const int* in_sizes, int n_in,
                              void* d_out, int out_size)
{
    const float* logits = (const float*)d_in[0];
    const float* u      = (const float*)d_in[1];
    const int*   cv     = (const int*)d_in[2];
    float* out = (float*)d_out;

    const long long n_probs  = (long long)DD * BB * VV;
    const long long n_tokens = (long long)BB * DD;

    float* tok_ptr   = nullptr;
    float* probs_ptr = nullptr;
    if ((long long)out_size == n_probs + n_tokens) {
        tok_ptr   = out;
        probs_ptr = out + n_tokens;
    } else if ((long long)out_size == n_probs) {
        probs_ptr = out;
    } else {
        tok_ptr = out;
    }

    decode_kernel<<<ROWS / 8, 256>>>(logits, u, cv,
                                     probs_ptr, probs_ptr != nullptr ? 1 : 0);
    if (tok_ptr != nullptr) {
        tokens_kernel<<<(BB * DD + 255) / 256, 256>>>(tok_ptr);
    }
}